// round 1
// baseline (speedup 1.0000x reference)
#include <cuda_runtime.h>
#include <math.h>

#define MDIM 12608   // 64 * 197
#define KDIM 768
#define NDIM 3072

#define BM 128
#define BN 128
#define BK 8
#define TM 8
#define TN 8

// Masked, transposed weight: g_wt[k * NDIM + n] = (weight * mask)[n, k]
__device__ float g_wt[KDIM * NDIM];

// ---------------------------------------------------------------------------
// Kernel 1: apply 2:4 mask (zero the 2 smallest-|w| per contiguous group of 4,
// ties broken toward lower index, matching jax.lax.top_k stability) and write
// the result transposed for coalesced GEMM B-loads.
// ---------------------------------------------------------------------------
__global__ void mask_transpose_kernel(const float* __restrict__ w) {
    const int ngroups = (NDIM * KDIM) / 4;
    int g = blockIdx.x * blockDim.x + threadIdx.x;
    if (g >= ngroups) return;
    const int gpr = KDIM / 4;           // groups per output row
    int o  = g / gpr;                   // output-feature index (row of weight)
    int gi = g - o * gpr;               // group index within the row

    const float4 wv = *reinterpret_cast<const float4*>(w + (size_t)o * KDIM + gi * 4);
    float v[4] = {wv.x, wv.y, wv.z, wv.w};
    float a[4] = {fabsf(v[0]), fabsf(v[1]), fabsf(v[2]), fabsf(v[3])};

    // i0 = argmin(|v|), ties -> lowest index (strict < keeps earlier index)
    int i0 = 0;
#pragma unroll
    for (int j = 1; j < 4; j++) if (a[j] < a[i0]) i0 = j;
    // i1 = argmin over the remaining three, ties -> lowest index
    int i1 = (i0 == 0) ? 1 : 0;
#pragma unroll
    for (int j = 0; j < 4; j++) {
        if (j == i0 || j == i1) continue;
        if (a[j] < a[i1]) i1 = j;
    }
    v[i0] = 0.0f;
    v[i1] = 0.0f;

    const int kbase = gi * 4;
#pragma unroll
    for (int j = 0; j < 4; j++)
        g_wt[(size_t)(kbase + j) * NDIM + o] = v[j];
}

// ---------------------------------------------------------------------------
// Kernel 2: fp32 SGEMM with fused bias.
//   C[m, n] = sum_k A[m, k] * g_wt[k, n] + bias[n]
// 128x128 CTA tile, BK=8, double-buffered smem, 256 threads, 8x8 per thread.
// ---------------------------------------------------------------------------
__global__ __launch_bounds__(256, 2)
void sgemm_bias_kernel(const float* __restrict__ A,
                       const float* __restrict__ bias,
                       float* __restrict__ C)
{
    __shared__ float As[2][BK][BM];   // transposed A tile: As[k][m]
    __shared__ float Bs[2][BK][BN];   // Bs[k][n]

    const int tid  = threadIdx.x;
    const int trow = tid >> 4;        // 0..15 (thread-tile row)
    const int tcol = tid & 15;        // 0..15 (thread-tile col)
    const int blockM = blockIdx.y * BM;
    const int blockN = blockIdx.x * BN;

    // Global-load assignments
    const int aRow = tid >> 1;        // 0..127
    const int aCol = (tid & 1) * 4;   // 0 or 4
    const int bRow = tid >> 5;        // 0..7
    const int bCol = (tid & 31) * 4;  // 0..124

    const int  gARow  = blockM + aRow;
    const bool aValid = (gARow < MDIM);
    const float* Aptr = A + (size_t)gARow * KDIM + aCol;
    const float* Bptr = g_wt + (size_t)bRow * NDIM + blockN + bCol;

    float acc[TM][TN];
#pragma unroll
    for (int i = 0; i < TM; i++)
#pragma unroll
        for (int j = 0; j < TN; j++) acc[i][j] = 0.0f;

    const float4 z4 = make_float4(0.f, 0.f, 0.f, 0.f);

    // --- preload tile 0 ---
    float4 av = aValid ? *reinterpret_cast<const float4*>(Aptr) : z4;
    float4 bv = *reinterpret_cast<const float4*>(Bptr);
    As[0][aCol + 0][aRow] = av.x;
    As[0][aCol + 1][aRow] = av.y;
    As[0][aCol + 2][aRow] = av.z;
    As[0][aCol + 3][aRow] = av.w;
    *reinterpret_cast<float4*>(&Bs[0][bRow][bCol]) = bv;
    __syncthreads();

    const int NTILES = KDIM / BK;     // 96
    int buf = 0;

    for (int t = 0; t < NTILES; t++) {
        // prefetch next tile into registers
        float4 avn = z4, bvn = z4;
        const bool hasNext = (t + 1 < NTILES);
        if (hasNext) {
            avn = aValid ? *reinterpret_cast<const float4*>(Aptr + (t + 1) * BK) : z4;
            bvn = *reinterpret_cast<const float4*>(Bptr + (size_t)(t + 1) * BK * NDIM);
        }

        // compute on current buffer
#pragma unroll
        for (int k = 0; k < BK; k++) {
            float4 a0 = *reinterpret_cast<const float4*>(&As[buf][k][trow * TM]);
            float4 a1 = *reinterpret_cast<const float4*>(&As[buf][k][trow * TM + 4]);
            float4 b0 = *reinterpret_cast<const float4*>(&Bs[buf][k][tcol * TN]);
            float4 b1 = *reinterpret_cast<const float4*>(&Bs[buf][k][tcol * TN + 4]);
            float areg[TM] = {a0.x, a0.y, a0.z, a0.w, a1.x, a1.y, a1.z, a1.w};
            float breg[TN] = {b0.x, b0.y, b0.z, b0.w, b1.x, b1.y, b1.z, b1.w};
#pragma unroll
            for (int i = 0; i < TM; i++)
#pragma unroll
                for (int j = 0; j < TN; j++)
                    acc[i][j] = fmaf(areg[i], breg[j], acc[i][j]);
        }

        if (hasNext) {
            const int nb = buf ^ 1;
            As[nb][aCol + 0][aRow] = avn.x;
            As[nb][aCol + 1][aRow] = avn.y;
            As[nb][aCol + 2][aRow] = avn.z;
            As[nb][aCol + 3][aRow] = avn.w;
            *reinterpret_cast<float4*>(&Bs[nb][bRow][bCol]) = bvn;
            __syncthreads();
            buf = nb;
        }
    }

    // --- epilogue: add bias, write back (guard ragged M) ---
    float bvals[TN];
#pragma unroll
    for (int j = 0; j < TN; j++)
        bvals[j] = bias[blockN + tcol * TN + j];

#pragma unroll
    for (int i = 0; i < TM; i++) {
        const int m = blockM + trow * TM + i;
        if (m < MDIM) {
            float* cp = C + (size_t)m * NDIM + blockN + tcol * TN;
            float4 o0 = make_float4(acc[i][0] + bvals[0], acc[i][1] + bvals[1],
                                    acc[i][2] + bvals[2], acc[i][3] + bvals[3]);
            float4 o1 = make_float4(acc[i][4] + bvals[4], acc[i][5] + bvals[5],
                                    acc[i][6] + bvals[6], acc[i][7] + bvals[7]);
            *reinterpret_cast<float4*>(cp)     = o0;
            *reinterpret_cast<float4*>(cp + 4) = o1;
        }
    }
}

// ---------------------------------------------------------------------------
extern "C" void kernel_launch(void* const* d_in, const int* in_sizes, int n_in,
                              void* d_out, int out_size) {
    const float* x    = (const float*)d_in[0];  // [64, 197, 768]
    const float* w    = (const float*)d_in[1];  // [3072, 768]
    const float* bias = (const float*)d_in[2];  // [3072]
    float* out        = (float*)d_out;          // [64, 197, 3072]

    const int ngroups = (NDIM * KDIM) / 4;
    mask_transpose_kernel<<<(ngroups + 255) / 256, 256>>>(w);

    dim3 grid(NDIM / BN, (MDIM + BM - 1) / BM);  // (24, 99)
    sgemm_bias_kernel<<<grid, 256>>>(x, bias, out);
}

// round 4
// speedup vs baseline: 3.0155x; 3.0155x over previous
#include <cuda_runtime.h>
#include <cuda_bf16.h>
#include <cstdint>
#include <math.h>

#define MDIM 12608     // 64 * 197
#define MPAD 12672     // 99 * 128 (padded M so GEMM A-loads need no predicates)
#define KDIM 768
#define NDIM 3072

#define BM 128
#define BN 128
#define BK 32
#define NT (KDIM / BK)      // 24 k-stages
#define STAGES 4

#define TILE_BYTES  (128 * 32 * 2)       // one bf16 tile: 8192 B
#define STAGE_BYTES (4 * TILE_BYTES)     // Ahi, Alo, Bhi, Blo: 32768 B
#define SMEM_TOTAL  (STAGES * STAGE_BYTES)  // 131072 B

// Split planes (bf16). X is zero-padded to MPAD rows.
__device__ __align__(16) __nv_bfloat16 g_xhi[(size_t)MPAD * KDIM];
__device__ __align__(16) __nv_bfloat16 g_xlo[(size_t)MPAD * KDIM];
__device__ __align__(16) __nv_bfloat16 g_whi[(size_t)NDIM * KDIM];
__device__ __align__(16) __nv_bfloat16 g_wlo[(size_t)NDIM * KDIM];

// ---------------- helpers ----------------
__device__ __forceinline__ void bsplit(float x, __nv_bfloat16& h, __nv_bfloat16& l) {
    h = __float2bfloat16_rn(x);
    l = __float2bfloat16_rn(x - __bfloat162float(h));
}

// 2:4 mask: zero the 2 smallest-|v| per group of 4; ties -> lower index pruned
__device__ __forceinline__ float4 mask24(float4 v) {
    float val[4] = {v.x, v.y, v.z, v.w};
    float a[4]   = {fabsf(v.x), fabsf(v.y), fabsf(v.z), fabsf(v.w)};
    int i0 = 0;
#pragma unroll
    for (int j = 1; j < 4; j++) if (a[j] < a[i0]) i0 = j;
    int i1 = (i0 == 0) ? 1 : 0;
#pragma unroll
    for (int j = 0; j < 4; j++) {
        if (j == i0 || j == i1) continue;
        if (a[j] < a[i1]) i1 = j;
    }
    val[i0] = 0.0f;
    val[i1] = 0.0f;
    return make_float4(val[0], val[1], val[2], val[3]);
}

__device__ __forceinline__ uint32_t smem_u32(const void* p) {
    uint32_t a;
    asm("{ .reg .u64 t; cvta.to.shared.u64 t, %1; cvt.u32.u64 %0, t; }" : "=r"(a) : "l"(p));
    return a;
}

#define CP16(dst, src) \
    asm volatile("cp.async.cg.shared.global [%0], [%1], 16;" :: "r"(dst), "l"(src) : "memory")

#define LDSM4(r, addr)                                                          \
    asm volatile("ldmatrix.sync.aligned.m8n8.x4.shared.b16 {%0,%1,%2,%3}, [%4];" \
                 : "=r"((r)[0]), "=r"((r)[1]), "=r"((r)[2]), "=r"((r)[3])       \
                 : "r"(addr))

#define MMA(d, a, b0, b1)                                                       \
    asm volatile("mma.sync.aligned.m16n8k16.row.col.f32.bf16.bf16.f32 "         \
                 "{%0,%1,%2,%3}, {%4,%5,%6,%7}, {%8,%9}, {%0,%1,%2,%3};"        \
                 : "+f"((d)[0]), "+f"((d)[1]), "+f"((d)[2]), "+f"((d)[3])       \
                 : "r"((a)[0]), "r"((a)[1]), "r"((a)[2]), "r"((a)[3]),          \
                   "r"(b0), "r"(b1))

// Swizzled byte offset within a [128 rows x 32 bf16] tile (64B rows).
// 16B segments; XOR seg with (row>>1)&3 so each 8-row ldmatrix group hits
// all 32 banks (even/odd rows split the 128B line, swizzle splits segments).
__device__ __forceinline__ uint32_t swz(int row, int seg) {
    return (uint32_t)(row * 64 + ((seg ^ ((row >> 1) & 3)) << 4));
}

// ---------------------------------------------------------------------------
// Prep 1: split X into bf16 hi/lo planes, zero-pad rows [MDIM, MPAD)
// ---------------------------------------------------------------------------
__global__ void split_x_kernel(const float* __restrict__ x) {
    int i4 = blockIdx.x * blockDim.x + threadIdx.x;
    if (i4 >= MPAD * KDIM / 4) return;
    int m = i4 / (KDIM / 4);
    float4 v = (m < MDIM) ? *reinterpret_cast<const float4*>(x + (size_t)i4 * 4)
                          : make_float4(0.f, 0.f, 0.f, 0.f);
    __nv_bfloat16 h[4], l[4];
    bsplit(v.x, h[0], l[0]); bsplit(v.y, h[1], l[1]);
    bsplit(v.z, h[2], l[2]); bsplit(v.w, h[3], l[3]);
    __nv_bfloat162* ph = reinterpret_cast<__nv_bfloat162*>(g_xhi + (size_t)i4 * 4);
    __nv_bfloat162* pl = reinterpret_cast<__nv_bfloat162*>(g_xlo + (size_t)i4 * 4);
    ph[0] = __nv_bfloat162(h[0], h[1]); ph[1] = __nv_bfloat162(h[2], h[3]);
    pl[0] = __nv_bfloat162(l[0], l[1]); pl[1] = __nv_bfloat162(l[2], l[3]);
}

// ---------------------------------------------------------------------------
// Prep 2: apply 2:4 mask to W, split into bf16 hi/lo planes
// ---------------------------------------------------------------------------
__global__ void mask_split_w_kernel(const float* __restrict__ w) {
    int g = blockIdx.x * blockDim.x + threadIdx.x;
    if (g >= NDIM * KDIM / 4) return;
    float4 v = mask24(*reinterpret_cast<const float4*>(w + (size_t)g * 4));
    __nv_bfloat16 h[4], l[4];
    bsplit(v.x, h[0], l[0]); bsplit(v.y, h[1], l[1]);
    bsplit(v.z, h[2], l[2]); bsplit(v.w, h[3], l[3]);
    __nv_bfloat162* ph = reinterpret_cast<__nv_bfloat162*>(g_whi + (size_t)g * 4);
    __nv_bfloat162* pl = reinterpret_cast<__nv_bfloat162*>(g_wlo + (size_t)g * 4);
    ph[0] = __nv_bfloat162(h[0], h[1]); ph[1] = __nv_bfloat162(h[2], h[3]);
    pl[0] = __nv_bfloat162(l[0], l[1]); pl[1] = __nv_bfloat162(l[2], l[3]);
}

// ---------------------------------------------------------------------------
// Main GEMM: out = Xhi*Whi^T + Xhi*Wlo^T + Xlo*Whi^T + bias  (fp32 accum)
// CTA 128x128, 8 warps (2x4), warp tile 64x32, BK=32, 4-stage cp.async.
// ---------------------------------------------------------------------------
__global__ __launch_bounds__(256, 1)
void gemm_split_bf16(const float* __restrict__ bias, float* __restrict__ out)
{
    extern __shared__ char smem[];
    const uint32_t sb = smem_u32(smem);
    const int tid = threadIdx.x;
    const int wid = tid >> 5;
    const int lid = tid & 31;
    const int blockM = blockIdx.y * BM;
    const int blockN = blockIdx.x * BN;

    const int wm = wid >> 2;      // 0..1 : 64-row slab
    const int wn = wid & 3;       // 0..3 : 32-col slab

    // ldmatrix lane addressing
    const int arow = lid & 15;           // m-row within 16-tile
    const int aseg = lid >> 4;           // k-half (0/1)
    const int brow = (lid & 7) | ((lid >> 4) << 3);  // n-row within 16-group
    const int bseg = (lid >> 3) & 1;                 // k-half

    // cp.async slot assignment: 512 (row,seg) slots per tile, 2 per thread
    auto load_stage = [&](int t, int buf) {
#pragma unroll
        for (int s = 0; s < 2; s++) {
            const int slot = tid + s * 256;
            const int row = slot >> 2;
            const int seg = slot & 3;
            const uint32_t d = sb + buf * STAGE_BYTES + swz(row, seg);
            const size_t goA = (size_t)(blockM + row) * KDIM + t * BK + seg * 8;
            const size_t goB = (size_t)(blockN + row) * KDIM + t * BK + seg * 8;
            CP16(d + 0 * TILE_BYTES, g_xhi + goA);
            CP16(d + 1 * TILE_BYTES, g_xlo + goA);
            CP16(d + 2 * TILE_BYTES, g_whi + goB);
            CP16(d + 3 * TILE_BYTES, g_wlo + goB);
        }
    };

    float acc[4][4][4];
#pragma unroll
    for (int i = 0; i < 4; i++)
#pragma unroll
        for (int j = 0; j < 4; j++)
#pragma unroll
            for (int k = 0; k < 4; k++) acc[i][j][k] = 0.0f;

    // prologue: stages 0..STAGES-2
#pragma unroll
    for (int s = 0; s < STAGES - 1; s++) {
        load_stage(s, s);
        asm volatile("cp.async.commit_group;" ::: "memory");
    }

    for (int t = 0; t < NT; t++) {
        asm volatile("cp.async.wait_group %0;" :: "n"(STAGES - 2) : "memory");
        __syncthreads();

        const uint32_t sbase = sb + (t % STAGES) * STAGE_BYTES;
#pragma unroll
        for (int ch = 0; ch < 2; ch++) {
            uint32_t ahi[4][4], alo[4][4], bhi[2][4], blo[2][4];
#pragma unroll
            for (int mi = 0; mi < 4; mi++) {
                const int row = wm * 64 + mi * 16 + arow;
                const uint32_t off = swz(row, ch * 2 + aseg);
                LDSM4(ahi[mi], sbase + 0 * TILE_BYTES + off);
                LDSM4(alo[mi], sbase + 1 * TILE_BYTES + off);
            }
#pragma unroll
            for (int ng = 0; ng < 2; ng++) {
                const int row = wn * 32 + ng * 16 + brow;
                const uint32_t off = swz(row, ch * 2 + bseg);
                LDSM4(bhi[ng], sbase + 2 * TILE_BYTES + off);
                LDSM4(blo[ng], sbase + 3 * TILE_BYTES + off);
            }
#pragma unroll
            for (int mi = 0; mi < 4; mi++)
#pragma unroll
                for (int ng = 0; ng < 2; ng++)
#pragma unroll
                    for (int sub = 0; sub < 2; sub++) {
                        float* d = acc[mi][ng * 2 + sub];
                        MMA(d, ahi[mi], bhi[ng][2 * sub], bhi[ng][2 * sub + 1]);
                        MMA(d, ahi[mi], blo[ng][2 * sub], blo[ng][2 * sub + 1]);
                        MMA(d, alo[mi], bhi[ng][2 * sub], bhi[ng][2 * sub + 1]);
                    }
        }

        const int nt = t + STAGES - 1;
        if (nt < NT) load_stage(nt, nt % STAGES);
        asm volatile("cp.async.commit_group;" ::: "memory");
    }

    // ---- epilogue: fused bias, float2 stores ----
    float2 bv[4];
#pragma unroll
    for (int ni = 0; ni < 4; ni++) {
        const int col = blockN + wn * 32 + ni * 8 + 2 * (lid & 3);
        bv[ni] = *reinterpret_cast<const float2*>(bias + col);
    }
#pragma unroll
    for (int mi = 0; mi < 4; mi++) {
        const int r0 = blockM + wm * 64 + mi * 16 + (lid >> 2);
        const int r1 = r0 + 8;
#pragma unroll
        for (int ni = 0; ni < 4; ni++) {
            const int col = blockN + wn * 32 + ni * 8 + 2 * (lid & 3);
            if (r0 < MDIM) {
                float2 o = make_float2(acc[mi][ni][0] + bv[ni].x,
                                       acc[mi][ni][1] + bv[ni].y);
                *reinterpret_cast<float2*>(out + (size_t)r0 * NDIM + col) = o;
            }
            if (r1 < MDIM) {
                float2 o = make_float2(acc[mi][ni][2] + bv[ni].x,
                                       acc[mi][ni][3] + bv[ni].y);
                *reinterpret_cast<float2*>(out + (size_t)r1 * NDIM + col) = o;
            }
        }
    }
}

// ---------------------------------------------------------------------------
extern "C" void kernel_launch(void* const* d_in, const int* in_sizes, int n_in,
                              void* d_out, int out_size) {
    const float* x    = (const float*)d_in[0];  // [64, 197, 768]
    const float* w    = (const float*)d_in[1];  // [3072, 768]
    const float* bias = (const float*)d_in[2];  // [3072]
    float* out        = (float*)d_out;          // [64, 197, 3072]

    split_x_kernel<<<(MPAD * KDIM / 4 + 255) / 256, 256>>>(x);
    mask_split_w_kernel<<<(NDIM * KDIM / 4 + 255) / 256, 256>>>(w);

    static bool attr_set = false;
    if (!attr_set) {
        cudaFuncSetAttribute(gemm_split_bf16,
                             cudaFuncAttributeMaxDynamicSharedMemorySize, SMEM_TOTAL);
        attr_set = true;
    }
    dim3 grid(NDIM / BN, (MPAD / BM));   // (24, 99)
    gemm_split_bf16<<<grid, 256, SMEM_TOTAL>>>(bias, out);
}